// round 1
// baseline (speedup 1.0000x reference)
#include <cuda_runtime.h>
#include <math.h>

// Problem constants (fixed-shape problem: volume 128^3, grid_sample align_corners=False)
#define XD 128
#define NDEPTH 222
// max_extent = sqrt(3*(64^2)) * 1.5
static constexpr double MAX_EXTENT_D = 166.27687752661222232;
static constexpr double DT_D         = 2.0 * MAX_EXTENT_D / (NDEPTH - 1);
static constexpr double SCALE_D      = 2.0 * MAX_EXTENT_D / NDEPTH;

__device__ __forceinline__ void slab_axis(float r, float b, float& tlo, float& thi, bool& empty) {
    // valid sample region per axis: position in (-1, 128) (outside -> both taps invalid -> 0)
    if (fabsf(r) > 1e-12f) {
        float inv = __frcp_rn(r);
        float ta = (-1.0f - b) * inv;
        float tb = (128.0f - b) * inv;
        tlo = fmaxf(tlo, fminf(ta, tb));
        thi = fminf(thi, fmaxf(ta, tb));
    } else if (b <= -1.0f || b >= 128.0f) {
        empty = true;
    }
}

__global__ void __launch_bounds__(128)
projector_kernel(const float* __restrict__ vol,
                 const float* __restrict__ vec,
                 float* __restrict__ out) {
    const int k = threadIdx.x;   // fastest output axis, maps to volume z (contiguous)
    const int j = blockIdx.x;
    const int n = blockIdx.y;

    const float* V = vec + n * 12;
    const float rx = __ldg(V + 0), ry = __ldg(V + 1), rz = __ldg(V + 2);
    const float dx = __ldg(V + 3), dy = __ldg(V + 4), dz = __ldg(V + 5);
    const float ux = __ldg(V + 6), uy = __ldg(V + 7), uz = __ldg(V + 8);
    const float vx = __ldg(V + 9), vy = __ldg(V + 10), vz = __ldg(V + 11);

    const float jc = (float)j - 63.5f;
    const float kc = (float)k - 63.5f;

    // base point in INDEX space: world + 63.5 per axis
    const float bx = fmaf(kc, vx, fmaf(jc, ux, dx)) + 63.5f;
    const float by = fmaf(kc, vy, fmaf(jc, uy, dy)) + 63.5f;
    const float bz = fmaf(kc, vz, fmaf(jc, uz, dz)) + 63.5f;

    const float t0 = (float)(-MAX_EXTENT_D);
    const float dt = (float)DT_D;

    // Ray-slab interval: samples outside contribute exactly zero.
    float tlo = -3.0e38f, thi = 3.0e38f;
    bool empty = false;
    slab_axis(rx, bx, tlo, thi, empty);
    slab_axis(ry, by, tlo, thi, empty);
    slab_axis(rz, bz, tlo, thi, empty);

    int i0 = 0, i1 = -1;
    if (!empty && thi >= tlo) {
        // pad by one step each side (boundary samples handled by per-tap predication)
        i0 = max(0, (int)ceilf((tlo - t0) / dt) - 1);
        i1 = min(NDEPTH - 1, (int)floorf((thi - t0) / dt) + 1);
    }

    float sum = 0.0f;
    #pragma unroll 2
    for (int i = i0; i <= i1; ++i) {
        const float t = fmaf((float)i, dt, t0);
        const float px = fmaf(t, rx, bx);
        const float py = fmaf(t, ry, by);
        const float pz = fmaf(t, rz, bz);

        const float x0f = floorf(px);
        const float y0f = floorf(py);
        const float z0f = floorf(pz);
        const float fx = px - x0f;
        const float fy = py - y0f;
        const float fz = pz - z0f;
        const int x0 = (int)x0f;
        const int y0 = (int)y0f;
        const int z0 = (int)z0f;

        const int a = x0 * (XD * XD) + y0 * XD + z0;

        const bool xv0 = ((unsigned)x0 < (unsigned)XD);
        const bool xv1 = ((unsigned)(x0 + 1) < (unsigned)XD);
        const bool yv0 = ((unsigned)y0 < (unsigned)XD);
        const bool yv1 = ((unsigned)(y0 + 1) < (unsigned)XD);
        const bool zv0 = ((unsigned)z0 < (unsigned)XD);
        const bool zv1 = ((unsigned)(z0 + 1) < (unsigned)XD);

        const float v000 = (xv0 & yv0 & zv0) ? __ldg(vol + a)                 : 0.0f;
        const float v001 = (xv0 & yv0 & zv1) ? __ldg(vol + a + 1)             : 0.0f;
        const float v010 = (xv0 & yv1 & zv0) ? __ldg(vol + a + XD)            : 0.0f;
        const float v011 = (xv0 & yv1 & zv1) ? __ldg(vol + a + XD + 1)        : 0.0f;
        const float v100 = (xv1 & yv0 & zv0) ? __ldg(vol + a + XD * XD)       : 0.0f;
        const float v101 = (xv1 & yv0 & zv1) ? __ldg(vol + a + XD * XD + 1)   : 0.0f;
        const float v110 = (xv1 & yv1 & zv0) ? __ldg(vol + a + XD * XD + XD)  : 0.0f;
        const float v111 = (xv1 & yv1 & zv1) ? __ldg(vol + a + XD * XD + XD + 1) : 0.0f;

        // trilinear via 7 lerps
        const float c00 = fmaf(fz, v001 - v000, v000);
        const float c01 = fmaf(fz, v011 - v010, v010);
        const float c10 = fmaf(fz, v101 - v100, v100);
        const float c11 = fmaf(fz, v111 - v110, v110);
        const float c0  = fmaf(fy, c01 - c00, c00);
        const float c1  = fmaf(fy, c11 - c10, c10);
        const float s   = fmaf(fx, c1 - c0, c0);
        sum += s;
    }

    out[((n * XD) + j) * XD + k] = sum * (float)SCALE_D;
}

extern "C" void kernel_launch(void* const* d_in, const int* in_sizes, int n_in,
                              void* d_out, int out_size) {
    const float* vol = (const float*)d_in[0];
    const float* vec = (const float*)d_in[1];
    float* out = (float*)d_out;

    const int N = in_sizes[1] / 12;   // number of views
    dim3 grid(XD, N);
    dim3 block(XD);
    projector_kernel<<<grid, block>>>(vol, vec, out);
}

// round 2
// speedup vs baseline: 2.8659x; 2.8659x over previous
#include <cuda_runtime.h>
#include <math.h>

#define XD 128
#define NDEPTH 222
// max_extent = sqrt(3*(64^2)) * 1.5
static constexpr double MAX_EXTENT_D = 166.27687752661222232;
static constexpr double DT_D         = 2.0 * MAX_EXTENT_D / (NDEPTH - 1);
static constexpr double SCALE_D      = 2.0 * MAX_EXTENT_D / NDEPTH;

__device__ __forceinline__ void slab_axis(float r, float b, float& tlo, float& thi, bool& empty) {
    if (fabsf(r) > 1e-12f) {
        float inv = __frcp_rn(r);
        float ta = (-1.0f - b) * inv;
        float tb = (128.0f - b) * inv;
        tlo = fmaxf(tlo, fminf(ta, tb));
        thi = fminf(thi, fmaxf(ta, tb));
    } else if (b <= -1.0f || b >= 128.0f) {
        empty = true;
    }
}

__global__ void __launch_bounds__(256)
projector_kernel(const float* __restrict__ vol,
                 const float* __restrict__ vec,
                 float* __restrict__ out) {
    const int tid = threadIdx.x;
    const int z   = tid & 127;   // pixel k / volume z index
    const int h   = tid >> 7;    // depth-split group (0 or 1)
    const int j   = blockIdx.x;
    const int n   = blockIdx.y;

    const float* V = vec + n * 12;
    const float rx = __ldg(V + 0), ry = __ldg(V + 1), rz = __ldg(V + 2);
    const float dx = __ldg(V + 3), dy = __ldg(V + 4), dz = __ldg(V + 5);
    const float ux = __ldg(V + 6), uy = __ldg(V + 7), uz = __ldg(V + 8);
    const float vx = __ldg(V + 9), vy = __ldg(V + 10), vz = __ldg(V + 11);

    const float t0 = (float)(-MAX_EXTENT_D);
    const float dt = (float)DT_D;
    const float jc = (float)j - 63.5f;

    __shared__ int4   As[NDEPTH + 2];
    __shared__ float4 Ws[NDEPTH + 2];
    __shared__ float  Red[2][XD];

    // Fast path: rays/planes axis-aligned in z -> per-block-uniform (x,y) sample,
    // and the z index is EXACTLY k with fz = 0 (single z-tap, weight 1).
    const bool fast = (rz == 0.0f) & (uz == 0.0f) & (dz == 0.0f) &
                      (vx == 0.0f) & (vy == 0.0f) & (vz == 1.0f);

    if (fast) {
        const float bx = fmaf(jc, ux, dx) + 63.5f;
        const float by = fmaf(jc, uy, dy) + 63.5f;

        float tlo = -3.0e38f, thi = 3.0e38f;
        bool empty = false;
        slab_axis(rx, bx, tlo, thi, empty);
        slab_axis(ry, by, tlo, thi, empty);

        int i0 = 0, cnt = 0;
        if (!empty && thi >= tlo) {
            i0 = max(0, (int)ceilf((tlo - t0) / dt) - 1);
            int i1 = min(NDEPTH - 1, (int)floorf((thi - t0) / dt) + 1);
            cnt = i1 - i0 + 1;
            if (cnt < 0) cnt = 0;
        }

        // Metadata phase: per-iteration row bases + bilinear weights (uniform data).
        for (int m = tid; m < cnt; m += 256) {
            const float t  = fmaf((float)(i0 + m), dt, t0);
            const float px = fmaf(t, rx, bx);
            const float py = fmaf(t, ry, by);
            const float x0f = floorf(px);
            const float y0f = floorf(py);
            const float fx = px - x0f;
            const float fy = py - y0f;
            const int x0 = (int)x0f;
            const int y0 = (int)y0f;
            const float wx0 = ((unsigned)x0       < (unsigned)XD) ? (1.0f - fx) : 0.0f;
            const float wx1 = ((unsigned)(x0 + 1) < (unsigned)XD) ? fx          : 0.0f;
            const float wy0 = ((unsigned)y0       < (unsigned)XD) ? (1.0f - fy) : 0.0f;
            const float wy1 = ((unsigned)(y0 + 1) < (unsigned)XD) ? fy          : 0.0f;
            const int xc0 = min(max(x0, 0), XD - 1);
            const int xc1 = min(max(x0 + 1, 0), XD - 1);
            const int yc0 = min(max(y0, 0), XD - 1);
            const int yc1 = min(max(y0 + 1, 0), XD - 1);
            As[m] = make_int4((xc0 * XD + yc0) * XD, (xc0 * XD + yc1) * XD,
                              (xc1 * XD + yc0) * XD, (xc1 * XD + yc1) * XD);
            Ws[m] = make_float4(wx0 * wy0, wx0 * wy1, wx1 * wy0, wx1 * wy1);
        }
        __syncthreads();

        // Mainloop: 4 coalesced row loads + 4 FMAs per depth step.
        float S = 0.0f;
        #pragma unroll 2
        for (int m = h; m < cnt; m += 2) {
            const int4   A = As[m];
            const float4 W = Ws[m];
            const float r0 = __ldg(vol + A.x + z);
            const float r1 = __ldg(vol + A.y + z);
            const float r2 = __ldg(vol + A.z + z);
            const float r3 = __ldg(vol + A.w + z);
            S = fmaf(W.x, r0, S);
            S = fmaf(W.y, r1, S);
            S = fmaf(W.z, r2, S);
            S = fmaf(W.w, r3, S);
        }
        Red[h][z] = S;
        __syncthreads();
        if (h == 0) {
            out[((n * XD) + j) * XD + z] = (Red[0][z] + Red[1][z]) * (float)SCALE_D;
        }
    } else {
        // General path: full trilinear gather per pixel, depth split across h.
        const float kc = (float)z - 63.5f;
        const float bx = fmaf(kc, vx, fmaf(jc, ux, dx)) + 63.5f;
        const float by = fmaf(kc, vy, fmaf(jc, uy, dy)) + 63.5f;
        const float bz = fmaf(kc, vz, fmaf(jc, uz, dz)) + 63.5f;

        float tlo = -3.0e38f, thi = 3.0e38f;
        bool empty = false;
        slab_axis(rx, bx, tlo, thi, empty);
        slab_axis(ry, by, tlo, thi, empty);
        slab_axis(rz, bz, tlo, thi, empty);

        int i0 = 0, i1 = -1;
        if (!empty && thi >= tlo) {
            i0 = max(0, (int)ceilf((tlo - t0) / dt) - 1);
            i1 = min(NDEPTH - 1, (int)floorf((thi - t0) / dt) + 1);
        }

        float sum = 0.0f;
        for (int i = i0 + h; i <= i1; i += 2) {
            const float t  = fmaf((float)i, dt, t0);
            const float px = fmaf(t, rx, bx);
            const float py = fmaf(t, ry, by);
            const float pz = fmaf(t, rz, bz);

            const float x0f = floorf(px);
            const float y0f = floorf(py);
            const float z0f = floorf(pz);
            const float fx = px - x0f;
            const float fy = py - y0f;
            const float fz = pz - z0f;
            const int x0 = (int)x0f;
            const int y0 = (int)y0f;
            const int z0 = (int)z0f;

            const int a = x0 * (XD * XD) + y0 * XD + z0;

            const bool xv0 = ((unsigned)x0 < (unsigned)XD);
            const bool xv1 = ((unsigned)(x0 + 1) < (unsigned)XD);
            const bool yv0 = ((unsigned)y0 < (unsigned)XD);
            const bool yv1 = ((unsigned)(y0 + 1) < (unsigned)XD);
            const bool zv0 = ((unsigned)z0 < (unsigned)XD);
            const bool zv1 = ((unsigned)(z0 + 1) < (unsigned)XD);

            const float v000 = (xv0 & yv0 & zv0) ? __ldg(vol + a)                  : 0.0f;
            const float v001 = (xv0 & yv0 & zv1) ? __ldg(vol + a + 1)              : 0.0f;
            const float v010 = (xv0 & yv1 & zv0) ? __ldg(vol + a + XD)             : 0.0f;
            const float v011 = (xv0 & yv1 & zv1) ? __ldg(vol + a + XD + 1)         : 0.0f;
            const float v100 = (xv1 & yv0 & zv0) ? __ldg(vol + a + XD * XD)        : 0.0f;
            const float v101 = (xv1 & yv0 & zv1) ? __ldg(vol + a + XD * XD + 1)    : 0.0f;
            const float v110 = (xv1 & yv1 & zv0) ? __ldg(vol + a + XD * XD + XD)   : 0.0f;
            const float v111 = (xv1 & yv1 & zv1) ? __ldg(vol + a + XD * XD + XD + 1) : 0.0f;

            const float c00 = fmaf(fz, v001 - v000, v000);
            const float c01 = fmaf(fz, v011 - v010, v010);
            const float c10 = fmaf(fz, v101 - v100, v100);
            const float c11 = fmaf(fz, v111 - v110, v110);
            const float c0  = fmaf(fy, c01 - c00, c00);
            const float c1  = fmaf(fy, c11 - c10, c10);
            sum += fmaf(fx, c1 - c0, c0);
        }
        Red[h][z] = sum;
        __syncthreads();
        if (h == 0) {
            out[((n * XD) + j) * XD + z] = (Red[0][z] + Red[1][z]) * (float)SCALE_D;
        }
    }
}

extern "C" void kernel_launch(void* const* d_in, const int* in_sizes, int n_in,
                              void* d_out, int out_size) {
    const float* vol = (const float*)d_in[0];
    const float* vec = (const float*)d_in[1];
    float* out = (float*)d_out;

    const int N = in_sizes[1] / 12;
    dim3 grid(XD, N);
    dim3 block(256);
    projector_kernel<<<grid, block>>>(vol, vec, out);
}

// round 3
// speedup vs baseline: 4.0517x; 1.4138x over previous
#include <cuda_runtime.h>
#include <math.h>

#define XD 128
#define NDEPTH 222
// max_extent = sqrt(3*(64^2)) * 1.5
static constexpr double MAX_EXTENT_D = 166.27687752661222232;
static constexpr double DT_D         = 2.0 * MAX_EXTENT_D / (NDEPTH - 1);
static constexpr double SCALE_D      = 2.0 * MAX_EXTENT_D / NDEPTH;

__device__ __forceinline__ void slab_axis(float r, float b, float& tlo, float& thi, bool& empty) {
    if (fabsf(r) > 1e-12f) {
        float inv = __frcp_rn(r);
        float ta = (-1.0f - b) * inv;
        float tb = (128.0f - b) * inv;
        tlo = fmaxf(tlo, fminf(ta, tb));
        thi = fminf(thi, fmaxf(ta, tb));
    } else if (b <= -1.0f || b >= 128.0f) {
        empty = true;
    }
}

__global__ void __launch_bounds__(256)
projector_kernel(const float* __restrict__ vol,
                 const float* __restrict__ vec,
                 float* __restrict__ out) {
    const int tid = threadIdx.x;
    const int j   = blockIdx.x;
    const int n   = blockIdx.y;

    const float* V = vec + n * 12;
    const float rx = __ldg(V + 0), ry = __ldg(V + 1), rz = __ldg(V + 2);
    const float dx = __ldg(V + 3), dy = __ldg(V + 4), dz = __ldg(V + 5);
    const float ux = __ldg(V + 6), uy = __ldg(V + 7), uz = __ldg(V + 8);
    const float vx = __ldg(V + 9), vy = __ldg(V + 10), vz = __ldg(V + 11);

    const float t0 = (float)(-MAX_EXTENT_D);
    const float dt = (float)DT_D;
    const float jc = (float)j - 63.5f;

    __shared__ int4   As[NDEPTH + 2];   // byte offsets of the 4 rows
    __shared__ float4 Ws[NDEPTH + 2];   // bilinear weights
    __shared__ float  Red[8][132];      // padded reduce buffer

    // Fast path: z-axis-aligned geometry -> per-block-uniform (x,y) sample,
    // z index is EXACTLY the pixel k with fz = 0 (single z-tap, weight 1).
    const bool fast = (rz == 0.0f) & (uz == 0.0f) & (dz == 0.0f) &
                      (vx == 0.0f) & (vy == 0.0f) & (vz == 1.0f);

    if (fast) {
        const int w    = tid >> 5;          // warp id: depth-split group (0..7)
        const int lane = tid & 31;          // covers z = 4*lane .. 4*lane+3

        const float bx = fmaf(jc, ux, dx) + 63.5f;
        const float by = fmaf(jc, uy, dy) + 63.5f;

        float tlo = -3.0e38f, thi = 3.0e38f;
        bool empty = false;
        slab_axis(rx, bx, tlo, thi, empty);
        slab_axis(ry, by, tlo, thi, empty);

        int i0 = 0, cnt = 0;
        if (!empty && thi >= tlo) {
            i0 = max(0, (int)ceilf((tlo - t0) / dt) - 1);
            int i1 = min(NDEPTH - 1, (int)floorf((thi - t0) / dt) + 1);
            cnt = i1 - i0 + 1;
            if (cnt < 0) cnt = 0;
        }

        // Metadata phase: per-step row byte-offsets + bilinear weights.
        for (int m = tid; m < cnt; m += 256) {
            const float t  = fmaf((float)(i0 + m), dt, t0);
            const float px = fmaf(t, rx, bx);
            const float py = fmaf(t, ry, by);
            const float x0f = floorf(px);
            const float y0f = floorf(py);
            const float fx = px - x0f;
            const float fy = py - y0f;
            const int x0 = (int)x0f;
            const int y0 = (int)y0f;
            const float wx0 = ((unsigned)x0       < (unsigned)XD) ? (1.0f - fx) : 0.0f;
            const float wx1 = ((unsigned)(x0 + 1) < (unsigned)XD) ? fx          : 0.0f;
            const float wy0 = ((unsigned)y0       < (unsigned)XD) ? (1.0f - fy) : 0.0f;
            const float wy1 = ((unsigned)(y0 + 1) < (unsigned)XD) ? fy          : 0.0f;
            const int xc0 = min(max(x0, 0), XD - 1);
            const int xc1 = min(max(x0 + 1, 0), XD - 1);
            const int yc0 = min(max(y0, 0), XD - 1);
            const int yc1 = min(max(y0 + 1, 0), XD - 1);
            As[m] = make_int4(((xc0 * XD + yc0) * XD) * 4, ((xc0 * XD + yc1) * XD) * 4,
                              ((xc1 * XD + yc0) * XD) * 4, ((xc1 * XD + yc1) * XD) * 4);
            Ws[m] = make_float4(wx0 * wy0, wx0 * wy1, wx1 * wy0, wx1 * wy1);
        }
        __syncthreads();

        // Mainloop: 4 x LDG.128 + 16 FFMA per depth step, per warp.
        const char* volb = (const char*)vol + (lane << 4);
        float4 S = make_float4(0.0f, 0.0f, 0.0f, 0.0f);
        #pragma unroll 2
        for (int m = w; m < cnt; m += 8) {
            const int4   A  = As[m];
            const float4 Wt = Ws[m];
            const float4 r0 = __ldg((const float4*)(volb + A.x));
            const float4 r1 = __ldg((const float4*)(volb + A.y));
            const float4 r2 = __ldg((const float4*)(volb + A.z));
            const float4 r3 = __ldg((const float4*)(volb + A.w));
            S.x = fmaf(Wt.x, r0.x, S.x); S.y = fmaf(Wt.x, r0.y, S.y);
            S.z = fmaf(Wt.x, r0.z, S.z); S.w = fmaf(Wt.x, r0.w, S.w);
            S.x = fmaf(Wt.y, r1.x, S.x); S.y = fmaf(Wt.y, r1.y, S.y);
            S.z = fmaf(Wt.y, r1.z, S.z); S.w = fmaf(Wt.y, r1.w, S.w);
            S.x = fmaf(Wt.z, r2.x, S.x); S.y = fmaf(Wt.z, r2.y, S.y);
            S.z = fmaf(Wt.z, r2.z, S.z); S.w = fmaf(Wt.z, r2.w, S.w);
            S.x = fmaf(Wt.w, r3.x, S.x); S.y = fmaf(Wt.w, r3.y, S.y);
            S.z = fmaf(Wt.w, r3.z, S.z); S.w = fmaf(Wt.w, r3.w, S.w);
        }
        Red[w][lane * 4 + 0] = S.x;
        Red[w][lane * 4 + 1] = S.y;
        Red[w][lane * 4 + 2] = S.z;
        Red[w][lane * 4 + 3] = S.w;
        __syncthreads();

        if (tid < XD) {
            float acc = 0.0f;
            #pragma unroll
            for (int g = 0; g < 8; ++g) acc += Red[g][tid];
            out[((n * XD) + j) * XD + tid] = acc * (float)SCALE_D;
        }
    } else {
        // General path: per-pixel trilinear gather, depth split across 2 groups.
        const int z = tid & 127;
        const int h = tid >> 7;
        const float kc = (float)z - 63.5f;
        const float bx = fmaf(kc, vx, fmaf(jc, ux, dx)) + 63.5f;
        const float by = fmaf(kc, vy, fmaf(jc, uy, dy)) + 63.5f;
        const float bz = fmaf(kc, vz, fmaf(jc, uz, dz)) + 63.5f;

        float tlo = -3.0e38f, thi = 3.0e38f;
        bool empty = false;
        slab_axis(rx, bx, tlo, thi, empty);
        slab_axis(ry, by, tlo, thi, empty);
        slab_axis(rz, bz, tlo, thi, empty);

        int i0 = 0, i1 = -1;
        if (!empty && thi >= tlo) {
            i0 = max(0, (int)ceilf((tlo - t0) / dt) - 1);
            i1 = min(NDEPTH - 1, (int)floorf((thi - t0) / dt) + 1);
        }

        float sum = 0.0f;
        for (int i = i0 + h; i <= i1; i += 2) {
            const float t  = fmaf((float)i, dt, t0);
            const float px = fmaf(t, rx, bx);
            const float py = fmaf(t, ry, by);
            const float pz = fmaf(t, rz, bz);

            const float x0f = floorf(px);
            const float y0f = floorf(py);
            const float z0f = floorf(pz);
            const float fx = px - x0f;
            const float fy = py - y0f;
            const float fz = pz - z0f;
            const int x0 = (int)x0f;
            const int y0 = (int)y0f;
            const int z0 = (int)z0f;

            const int a = x0 * (XD * XD) + y0 * XD + z0;

            const bool xv0 = ((unsigned)x0 < (unsigned)XD);
            const bool xv1 = ((unsigned)(x0 + 1) < (unsigned)XD);
            const bool yv0 = ((unsigned)y0 < (unsigned)XD);
            const bool yv1 = ((unsigned)(y0 + 1) < (unsigned)XD);
            const bool zv0 = ((unsigned)z0 < (unsigned)XD);
            const bool zv1 = ((unsigned)(z0 + 1) < (unsigned)XD);

            const float v000 = (xv0 & yv0 & zv0) ? __ldg(vol + a)                    : 0.0f;
            const float v001 = (xv0 & yv0 & zv1) ? __ldg(vol + a + 1)                : 0.0f;
            const float v010 = (xv0 & yv1 & zv0) ? __ldg(vol + a + XD)               : 0.0f;
            const float v011 = (xv0 & yv1 & zv1) ? __ldg(vol + a + XD + 1)           : 0.0f;
            const float v100 = (xv1 & yv0 & zv0) ? __ldg(vol + a + XD * XD)          : 0.0f;
            const float v101 = (xv1 & yv0 & zv1) ? __ldg(vol + a + XD * XD + 1)      : 0.0f;
            const float v110 = (xv1 & yv1 & zv0) ? __ldg(vol + a + XD * XD + XD)     : 0.0f;
            const float v111 = (xv1 & yv1 & zv1) ? __ldg(vol + a + XD * XD + XD + 1) : 0.0f;

            const float c00 = fmaf(fz, v001 - v000, v000);
            const float c01 = fmaf(fz, v011 - v010, v010);
            const float c10 = fmaf(fz, v101 - v100, v100);
            const float c11 = fmaf(fz, v111 - v110, v110);
            const float c0  = fmaf(fy, c01 - c00, c00);
            const float c1  = fmaf(fy, c11 - c10, c10);
            sum += fmaf(fx, c1 - c0, c0);
        }
        Red[h][z] = sum;
        __syncthreads();
        if (h == 0) {
            out[((n * XD) + j) * XD + z] = (Red[0][z] + Red[1][z]) * (float)SCALE_D;
        }
    }
}

extern "C" void kernel_launch(void* const* d_in, const int* in_sizes, int n_in,
                              void* d_out, int out_size) {
    const float* vol = (const float*)d_in[0];
    const float* vec = (const float*)d_in[1];
    float* out = (float*)d_out;

    const int N = in_sizes[1] / 12;
    dim3 grid(XD, N);
    dim3 block(256);
    projector_kernel<<<grid, block>>>(vol, vec, out);
}

// round 4
// speedup vs baseline: 4.7118x; 1.1629x over previous
#include <cuda_runtime.h>
#include <math.h>

#define XD 128
#define NDEPTH 222
#define MPAD 240
// max_extent = sqrt(3*(64^2)) * 1.5
static constexpr double MAX_EXTENT_D = 166.27687752661222232;
static constexpr double DT_D         = 2.0 * MAX_EXTENT_D / (NDEPTH - 1);
static constexpr double SCALE_D      = 2.0 * MAX_EXTENT_D / NDEPTH;

__device__ __forceinline__ void slab_axis(float r, float b, float& tlo, float& thi, bool& empty) {
    if (fabsf(r) > 1e-12f) {
        float inv = __frcp_rn(r);
        float ta = (-1.0f - b) * inv;
        float tb = (128.0f - b) * inv;
        tlo = fmaxf(tlo, fminf(ta, tb));
        thi = fminf(thi, fmaxf(ta, tb));
    } else if (b <= -1.0f || b >= 128.0f) {
        empty = true;
    }
}

__global__ void __launch_bounds__(128, 8)
projector_kernel(const float* __restrict__ vol,
                 const float* __restrict__ vec,
                 float* __restrict__ out) {
    const int tid = threadIdx.x;
    const int j   = blockIdx.x;
    const int n   = blockIdx.y;

    const float* V = vec + n * 12;
    const float rx = __ldg(V + 0), ry = __ldg(V + 1), rz = __ldg(V + 2);
    const float dx = __ldg(V + 3), dy = __ldg(V + 4), dz = __ldg(V + 5);
    const float ux = __ldg(V + 6), uy = __ldg(V + 7), uz = __ldg(V + 8);
    const float vx = __ldg(V + 9), vy = __ldg(V + 10), vz = __ldg(V + 11);

    const float t0 = (float)(-MAX_EXTENT_D);
    const float dt = (float)DT_D;
    const float jc = (float)j - 63.5f;

    __shared__ int4   As[MPAD];    // byte offsets of the 4 rows
    __shared__ float4 Ws[MPAD];    // bilinear weights
    __shared__ float  Red[4][132]; // padded reduce buffer

    // Fast path: z-axis-aligned geometry -> per-block-uniform (x,y) sample,
    // z index is EXACTLY the pixel k with fz = 0 (single z-tap, weight 1).
    const bool fast = (rz == 0.0f) & (uz == 0.0f) & (dz == 0.0f) &
                      (vx == 0.0f) & (vy == 0.0f) & (vz == 1.0f);

    if (fast) {
        const int w    = tid >> 5;   // warp id (0..3): depth-split group
        const int lane = tid & 31;   // covers z = 4*lane .. 4*lane+3

        const float bx = fmaf(jc, ux, dx) + 63.5f;
        const float by = fmaf(jc, uy, dy) + 63.5f;

        float tlo = -3.0e38f, thi = 3.0e38f;
        bool empty = false;
        slab_axis(rx, bx, tlo, thi, empty);
        slab_axis(ry, by, tlo, thi, empty);

        int i0 = 0, cnt = 0;
        if (!empty && thi >= tlo) {
            i0 = max(0, (int)ceilf((tlo - t0) / dt) - 1);
            int i1 = min(NDEPTH - 1, (int)floorf((thi - t0) / dt) + 1);
            cnt = i1 - i0 + 1;
            if (cnt < 0) cnt = 0;
        }
        const int cntPad = (cnt + 7) & ~7;   // pad to unroll granularity (zero-weight tail)

        // Metadata phase: per-step row byte-offsets + bilinear weights.
        for (int m = tid; m < cntPad; m += 128) {
            if (m < cnt) {
                const float t  = fmaf((float)(i0 + m), dt, t0);
                const float px = fmaf(t, rx, bx);
                const float py = fmaf(t, ry, by);
                const float x0f = floorf(px);
                const float y0f = floorf(py);
                const float fx = px - x0f;
                const float fy = py - y0f;
                const int x0 = (int)x0f;
                const int y0 = (int)y0f;
                const float wx0 = ((unsigned)x0       < (unsigned)XD) ? (1.0f - fx) : 0.0f;
                const float wx1 = ((unsigned)(x0 + 1) < (unsigned)XD) ? fx          : 0.0f;
                const float wy0 = ((unsigned)y0       < (unsigned)XD) ? (1.0f - fy) : 0.0f;
                const float wy1 = ((unsigned)(y0 + 1) < (unsigned)XD) ? fy          : 0.0f;
                const int xc0 = min(max(x0, 0), XD - 1);
                const int xc1 = min(max(x0 + 1, 0), XD - 1);
                const int yc0 = min(max(y0, 0), XD - 1);
                const int yc1 = min(max(y0 + 1, 0), XD - 1);
                As[m] = make_int4(((xc0 * XD + yc0) * XD) * 4, ((xc0 * XD + yc1) * XD) * 4,
                                  ((xc1 * XD + yc0) * XD) * 4, ((xc1 * XD + yc1) * XD) * 4);
                Ws[m] = make_float4(wx0 * wy0, wx0 * wy1, wx1 * wy0, wx1 * wy1);
            } else {
                As[m] = make_int4(0, 0, 0, 0);
                Ws[m] = make_float4(0.0f, 0.0f, 0.0f, 0.0f);
            }
        }
        __syncthreads();

        // Mainloop: 2 depth steps per trip -> 8 x LDG.128 in flight + 32 FFMA.
        const char* volb = (const char*)vol + (lane << 4);
        float4 S = make_float4(0.0f, 0.0f, 0.0f, 0.0f);
        for (int m = 2 * w; m < cntPad; m += 8) {
            const int4   A0 = As[m];
            const int4   A1 = As[m + 1];
            const float4 W0 = Ws[m];
            const float4 W1 = Ws[m + 1];
            const float4 r0 = __ldg((const float4*)(volb + A0.x));
            const float4 r1 = __ldg((const float4*)(volb + A0.y));
            const float4 r2 = __ldg((const float4*)(volb + A0.z));
            const float4 r3 = __ldg((const float4*)(volb + A0.w));
            const float4 r4 = __ldg((const float4*)(volb + A1.x));
            const float4 r5 = __ldg((const float4*)(volb + A1.y));
            const float4 r6 = __ldg((const float4*)(volb + A1.z));
            const float4 r7 = __ldg((const float4*)(volb + A1.w));
            S.x = fmaf(W0.x, r0.x, S.x); S.y = fmaf(W0.x, r0.y, S.y);
            S.z = fmaf(W0.x, r0.z, S.z); S.w = fmaf(W0.x, r0.w, S.w);
            S.x = fmaf(W0.y, r1.x, S.x); S.y = fmaf(W0.y, r1.y, S.y);
            S.z = fmaf(W0.y, r1.z, S.z); S.w = fmaf(W0.y, r1.w, S.w);
            S.x = fmaf(W0.z, r2.x, S.x); S.y = fmaf(W0.z, r2.y, S.y);
            S.z = fmaf(W0.z, r2.z, S.z); S.w = fmaf(W0.z, r2.w, S.w);
            S.x = fmaf(W0.w, r3.x, S.x); S.y = fmaf(W0.w, r3.y, S.y);
            S.z = fmaf(W0.w, r3.z, S.z); S.w = fmaf(W0.w, r3.w, S.w);
            S.x = fmaf(W1.x, r4.x, S.x); S.y = fmaf(W1.x, r4.y, S.y);
            S.z = fmaf(W1.x, r4.z, S.z); S.w = fmaf(W1.x, r4.w, S.w);
            S.x = fmaf(W1.y, r5.x, S.x); S.y = fmaf(W1.y, r5.y, S.y);
            S.z = fmaf(W1.y, r5.z, S.z); S.w = fmaf(W1.y, r5.w, S.w);
            S.x = fmaf(W1.z, r6.x, S.x); S.y = fmaf(W1.z, r6.y, S.y);
            S.z = fmaf(W1.z, r6.z, S.z); S.w = fmaf(W1.z, r6.w, S.w);
            S.x = fmaf(W1.w, r7.x, S.x); S.y = fmaf(W1.w, r7.y, S.y);
            S.z = fmaf(W1.w, r7.z, S.z); S.w = fmaf(W1.w, r7.w, S.w);
        }
        Red[w][lane * 4 + 0] = S.x;
        Red[w][lane * 4 + 1] = S.y;
        Red[w][lane * 4 + 2] = S.z;
        Red[w][lane * 4 + 3] = S.w;
        __syncthreads();

        const float acc = Red[0][tid] + Red[1][tid] + Red[2][tid] + Red[3][tid];
        out[((n * XD) + j) * XD + tid] = acc * (float)SCALE_D;
    } else {
        // General path: per-pixel trilinear gather (one thread per z, full depth).
        const int z = tid;
        const float kc = (float)z - 63.5f;
        const float bx = fmaf(kc, vx, fmaf(jc, ux, dx)) + 63.5f;
        const float by = fmaf(kc, vy, fmaf(jc, uy, dy)) + 63.5f;
        const float bz = fmaf(kc, vz, fmaf(jc, uz, dz)) + 63.5f;

        float tlo = -3.0e38f, thi = 3.0e38f;
        bool empty = false;
        slab_axis(rx, bx, tlo, thi, empty);
        slab_axis(ry, by, tlo, thi, empty);
        slab_axis(rz, bz, tlo, thi, empty);

        int i0 = 0, i1 = -1;
        if (!empty && thi >= tlo) {
            i0 = max(0, (int)ceilf((tlo - t0) / dt) - 1);
            i1 = min(NDEPTH - 1, (int)floorf((thi - t0) / dt) + 1);
        }

        float sum = 0.0f;
        for (int i = i0; i <= i1; ++i) {
            const float t  = fmaf((float)i, dt, t0);
            const float px = fmaf(t, rx, bx);
            const float py = fmaf(t, ry, by);
            const float pz = fmaf(t, rz, bz);

            const float x0f = floorf(px);
            const float y0f = floorf(py);
            const float z0f = floorf(pz);
            const float fx = px - x0f;
            const float fy = py - y0f;
            const float fz = pz - z0f;
            const int x0 = (int)x0f;
            const int y0 = (int)y0f;
            const int z0 = (int)z0f;

            const int a = x0 * (XD * XD) + y0 * XD + z0;

            const bool xv0 = ((unsigned)x0 < (unsigned)XD);
            const bool xv1 = ((unsigned)(x0 + 1) < (unsigned)XD);
            const bool yv0 = ((unsigned)y0 < (unsigned)XD);
            const bool yv1 = ((unsigned)(y0 + 1) < (unsigned)XD);
            const bool zv0 = ((unsigned)z0 < (unsigned)XD);
            const bool zv1 = ((unsigned)(z0 + 1) < (unsigned)XD);

            const float v000 = (xv0 & yv0 & zv0) ? __ldg(vol + a)                    : 0.0f;
            const float v001 = (xv0 & yv0 & zv1) ? __ldg(vol + a + 1)                : 0.0f;
            const float v010 = (xv0 & yv1 & zv0) ? __ldg(vol + a + XD)               : 0.0f;
            const float v011 = (xv0 & yv1 & zv1) ? __ldg(vol + a + XD + 1)           : 0.0f;
            const float v100 = (xv1 & yv0 & zv0) ? __ldg(vol + a + XD * XD)          : 0.0f;
            const float v101 = (xv1 & yv0 & zv1) ? __ldg(vol + a + XD * XD + 1)      : 0.0f;
            const float v110 = (xv1 & yv1 & zv0) ? __ldg(vol + a + XD * XD + XD)     : 0.0f;
            const float v111 = (xv1 & yv1 & zv1) ? __ldg(vol + a + XD * XD + XD + 1) : 0.0f;

            const float c00 = fmaf(fz, v001 - v000, v000);
            const float c01 = fmaf(fz, v011 - v010, v010);
            const float c10 = fmaf(fz, v101 - v100, v100);
            const float c11 = fmaf(fz, v111 - v110, v110);
            const float c0  = fmaf(fy, c01 - c00, c00);
            const float c1  = fmaf(fy, c11 - c10, c10);
            sum += fmaf(fx, c1 - c0, c0);
        }
        out[((n * XD) + j) * XD + z] = sum * (float)SCALE_D;
    }
}

extern "C" void kernel_launch(void* const* d_in, const int* in_sizes, int n_in,
                              void* d_out, int out_size) {
    const float* vol = (const float*)d_in[0];
    const float* vec = (const float*)d_in[1];
    float* out = (float*)d_out;

    const int N = in_sizes[1] / 12;
    dim3 grid(XD, N);
    dim3 block(128);
    projector_kernel<<<grid, block>>>(vol, vec, out);
}